// round 5
// baseline (speedup 1.0000x reference)
#include <cuda_runtime.h>

// Problem: x (2,128,512,512) f32.
//   edge = sum_o |conv(sum_c x, sobel_o)|  (channel-independent)
//   out  = maxpool2x2(edge) broadcast to (2,128,256,256)
//
// Pipelined: 4 chunks (batch x spatial-half, 2-row halo).
//   cs chunk (DRAM-read bound, stream 0)  -> g_part[4][b][rows]
//   ec chunk (L2-write bound, stream s2)  -> overlaps next cs chunk
// Fork-join via events so the whole thing stays graph-capturable.

#define S_SPATIAL   (512 * 512)
#define S_SPATIAL4  (S_SPATIAL / 4)   // 65536
#define NCH         128
#define NB          2

__device__ float g_part[4 * NB * S_SPATIAL];   // 8 MB scratch: [cg][b][spatial]

// ---------------- cs chunk: 32-channel partial sums over a row range ----------------
__global__ void __launch_bounds__(256) k_chansum(const float4* __restrict__ x,
                                                 int b, int row0, int nrows) {
    int idx = blockIdx.x * blockDim.x + threadIdx.x;
    if (idx >= nrows * 512) return;          // nrows*128 f4-cols * 4 channel groups
    int f4   = idx & 127;
    int t    = idx >> 7;
    int rowl = t % nrows;
    int cg   = t / nrows;                    // 0..3
    int sp4  = (row0 + rowl) * 128 + f4;
    const float4* p = x + (size_t)(b * NCH + cg * 32) * S_SPATIAL4 + sp4;
    float4 acc = make_float4(0.f, 0.f, 0.f, 0.f);
#pragma unroll 8
    for (int c = 0; c < 32; c++) {
        float4 v = p[(size_t)c * S_SPATIAL4];
        acc.x += v.x; acc.y += v.y; acc.z += v.z; acc.w += v.w;
    }
    ((float4*)g_part)[((cg * NB + b) << 16) + sp4] = acc;
}

// ---------------- ec chunk: edge+pool one row, broadcast 128 channels ----------------
__device__ __forceinline__ float edge_at(const float* r0, const float* r1,
                                         const float* r2, int x0) {
    float a = r0[x0],  bb = r0[x0+1], c = r0[x0+2];
    float d = r1[x0],                  f = r1[x0+2];
    float g = r2[x0],  h = r2[x0+1],  i = r2[x0+2];
    // XLA conv = cross-correlation (no kernel flip)
    float e0 = -a + c - 2.f*d + 2.f*f - g + i;
    float e1 =  a + 2.f*bb + c - g - 2.f*h - i;
    float e2 =  2.f*a + bb + d - f - h - 2.f*i;
    float e3 = -bb - 2.f*c + d - f + 2.f*g + h;
    return fabsf(e0) + fabsf(e1) + fabsf(e2) + fabsf(e3);
}

#define SROW_W 520

__global__ void __launch_bounds__(256) k_edgecast(float4* __restrict__ out,
                                                  int b, int py0) {
    int py  = py0 + blockIdx.x;              // pooled row
    int tid = threadIdx.x;                   // = px, 0..255

    __shared__ float srow[4][SROW_W];        // input rows 2py-1..2py+2, x shifted +1
    __shared__ float row[256];               // pooled edge row

    const float4* P = (const float4*)g_part;
#pragma unroll
    for (int k = tid; k < 512; k += 256) {
        int r  = k >> 7;                     // 0..3
        int f4 = k & 127;
        int y  = 2 * py - 1 + r;
        float4 v = make_float4(0.f, 0.f, 0.f, 0.f);
        if (y >= 0 && y < 512) {
            int sp4 = y * 128 + f4;
            float4 v0 = __ldg(P + ((0 * NB + b) << 16) + sp4);
            float4 v1 = __ldg(P + ((1 * NB + b) << 16) + sp4);
            float4 v2 = __ldg(P + ((2 * NB + b) << 16) + sp4);
            float4 v3 = __ldg(P + ((3 * NB + b) << 16) + sp4);
            v.x = (v0.x + v1.x) + (v2.x + v3.x);
            v.y = (v0.y + v1.y) + (v2.y + v3.y);
            v.z = (v0.z + v1.z) + (v2.z + v3.z);
            v.w = (v0.w + v1.w) + (v2.w + v3.w);
        }
        float* dst = &srow[r][1 + 4 * f4];
        dst[0] = v.x; dst[1] = v.y; dst[2] = v.z; dst[3] = v.w;
    }
    if (tid < 8) {                           // halo cols x=-1, x=512 are zero
        int r = tid >> 1;
        srow[r][(tid & 1) ? 513 : 0] = 0.f;
    }
    __syncthreads();

    {
        int xb = 2 * tid;
        const float *r0 = srow[0], *r1 = srow[1], *r2 = srow[2], *r3 = srow[3];
        row[tid] = fmaxf(
            fmaxf(edge_at(r0, r1, r2, xb), edge_at(r0, r1, r2, xb + 1)),
            fmaxf(edge_at(r1, r2, r3, xb), edge_at(r1, r2, r3, xb + 1)));
    }
    __syncthreads();

    // Broadcast write: 128 channels x 64 float4 = 8192 float4 / block.
    int px4  = tid & 63;
    int csub = tid >> 6;                     // 0..3
    float4 v = ((const float4*)row)[px4];
    float4* o = out + ((size_t)(b * NCH + csub) * 256 + py) * 64 + px4;
#pragma unroll
    for (int i = 0; i < 32; i++) {
        __stcs(o, v);                        // evict-first: eager writeback
        o += (size_t)4 * 256 * 64;           // advance 4 channels
    }
}

extern "C" void kernel_launch(void* const* d_in, const int* in_sizes, int n_in,
                              void* d_out, int out_size) {
    const float4* x = (const float4*)d_in[0];
    float4* out = (float4*)d_out;

    // Fork-join second stream (created per call; intentionally leaked — a
    // handful of calls total, no device-memory allocation involved).
    cudaStream_t s2;
    cudaStreamCreateWithFlags(&s2, cudaStreamNonBlocking);
    cudaEvent_t ev[4], evj;
    for (int i = 0; i < 4; i++) cudaEventCreateWithFlags(&ev[i], cudaEventDisableTiming);
    cudaEventCreateWithFlags(&evj, cudaEventDisableTiming);

    // Chunks: (b, half). cs covers rows with 2-row halo so ec(b,h) only
    // needs cs chunks <= (b,h). Halo rows are written twice with identical
    // values (same summation order) — benign.
    const int row0s[2]  = {0, 254};
    const int nrows     = 258;               // both chunks
    const int csgrid    = (nrows * 512 + 255) / 256;   // 516

    for (int chunk = 0; chunk < 4; chunk++) {
        int b = chunk >> 1, h = chunk & 1;
        k_chansum<<<csgrid, 256>>>(x, b, row0s[h], nrows);
        cudaEventRecord(ev[chunk], 0);
        cudaStreamWaitEvent(s2, ev[chunk], 0);
        k_edgecast<<<128, 256, 0, s2>>>(out, b, h * 128);
    }
    cudaEventRecord(evj, s2);
    cudaStreamWaitEvent(0, evj, 0);
}